// round 1
// baseline (speedup 1.0000x reference)
#include <cuda_runtime.h>
#include <cuda_bf16.h>

#define RADIUS 4
#define DD 9            // 2*RADIUS+1
#define NB 16
#define NC 256
#define NH 96
#define NW 96
#define TYR 4           // output rows per CTA
#define PX 8            // pixels per thread along x
#define NG (NW / PX)    // 12 x-groups per row
#define CC 8            // channels staged per smem chunk
#define NTHREADS (NG * DD * TYR)   // 432
#define TH (TYR + 2 * RADIUS)      // 12 halo rows
#define TW (NW + 2 * RADIUS)       // 104 halo cols

__global__ __launch_bounds__(NTHREADS, 1)
void corr_kernel(const float* __restrict__ fs, const float* __restrict__ ft,
                 float* __restrict__ out)
{
    extern __shared__ float smem[];
    float* t_sh = smem;                    // [CC][TH][TW]
    float* s_sh = smem + CC * TH * TW;     // [CC][TYR][NW]

    const int b   = blockIdx.y;
    const int y0  = blockIdx.x * TYR;
    const int tid = threadIdx.x;
    const int g   = tid % NG;              // x-group
    const int dy  = (tid / NG) % DD;       // this thread's dy plane
    const int r   = tid / (NG * DD);       // row within tile
    const int x0  = g * PX;

    float acc[PX * DD];
#pragma unroll
    for (int i = 0; i < PX * DD; ++i) acc[i] = 0.f;

    const float* fs_b = fs + (size_t)b * NC * NH * NW;
    const float* ft_b = ft + (size_t)b * NC * NH * NW;

    for (int c0 = 0; c0 < NC; c0 += CC) {
        __syncthreads();   // previous chunk's readers done

        // ---- stage t halo chunk: rows y0-4 .. y0+7, cols -4 .. 99, zero padded
        for (int idx = tid; idx < CC * TH * TW; idx += NTHREADS) {
            int c   = idx / (TH * TW);
            int rem = idx - c * (TH * TW);
            int row = rem / TW;
            int col = rem - row * TW;
            int gr  = y0 + row - RADIUS;
            int gc  = col - RADIUS;
            float v = 0.f;
            if ((unsigned)gr < NH && (unsigned)gc < NW)
                v = ft_b[((c0 + c) * NH + gr) * NW + gc];
            t_sh[idx] = v;
        }
        // ---- stage s chunk: rows y0 .. y0+3, cols 0..95
        for (int idx = tid; idx < CC * TYR * NW; idx += NTHREADS) {
            int c   = idx / (TYR * NW);
            int rem = idx - c * (TYR * NW);
            s_sh[idx] = fs_b[(c0 + c) * NH * NW + y0 * NW + rem];
        }
        __syncthreads();

#pragma unroll
        for (int c = 0; c < CC; ++c) {
            // t row for this thread: global row y0+r+dy-4 -> smem row (r+dy)
            // smem col j holds global col j-4; need cols x0-4..x0+11 -> j = x0..x0+15
            const float* tp = t_sh + (c * TH + (r + dy)) * TW + x0;
            const float* sp = s_sh + (c * TYR + r) * NW + x0;

            float4 t0 = *(const float4*)(tp);
            float4 t1 = *(const float4*)(tp + 4);
            float4 t2 = *(const float4*)(tp + 8);
            float4 t3 = *(const float4*)(tp + 12);
            float tt[16] = {t0.x, t0.y, t0.z, t0.w,  t1.x, t1.y, t1.z, t1.w,
                            t2.x, t2.y, t2.z, t2.w,  t3.x, t3.y, t3.z, t3.w};

            float4 s0 = *(const float4*)(sp);
            float4 s1 = *(const float4*)(sp + 4);
            float ss[8] = {s0.x, s0.y, s0.z, s0.w,  s1.x, s1.y, s1.z, s1.w};

#pragma unroll
            for (int p = 0; p < PX; ++p) {
#pragma unroll
                for (int dx = 0; dx < DD; ++dx) {
                    acc[p * DD + dx] = fmaf(ss[p], tt[p + dx], acc[p * DD + dx]);
                }
            }
        }
    }

    // ---- epilogue: out[b, dy*9+dx, y, x0..x0+7], scaled by 1/C
    const float scale = 1.0f / (float)NC;
    const int y = y0 + r;
    float* ob = out + (((size_t)b * (DD * DD) + dy * DD) * NH + y) * NW + x0;
#pragma unroll
    for (int dx = 0; dx < DD; ++dx) {
        float4 o0, o1;
        o0.x = acc[0 * DD + dx] * scale;
        o0.y = acc[1 * DD + dx] * scale;
        o0.z = acc[2 * DD + dx] * scale;
        o0.w = acc[3 * DD + dx] * scale;
        o1.x = acc[4 * DD + dx] * scale;
        o1.y = acc[5 * DD + dx] * scale;
        o1.z = acc[6 * DD + dx] * scale;
        o1.w = acc[7 * DD + dx] * scale;
        float* op = ob + (size_t)dx * NH * NW;
        *(float4*)(op)     = o0;
        *(float4*)(op + 4) = o1;
    }
}

extern "C" void kernel_launch(void* const* d_in, const int* in_sizes, int n_in,
                              void* d_out, int out_size)
{
    const float* fs = (const float*)d_in[0];   // feat_s
    const float* ft = (const float*)d_in[1];   // feat_t
    float* out = (float*)d_out;

    size_t smem_bytes = (size_t)(CC * TH * TW + CC * TYR * NW) * sizeof(float); // 52224
    cudaFuncSetAttribute(corr_kernel, cudaFuncAttributeMaxDynamicSharedMemorySize,
                         (int)smem_bytes);

    dim3 grid(NH / TYR, NB);   // (24, 16)
    corr_kernel<<<grid, NTHREADS, smem_bytes>>>(fs, ft, out);
}

// round 2
// speedup vs baseline: 2.2682x; 2.2682x over previous
#include <cuda_runtime.h>
#include <cstdint>

#define RADIUS 4
#define DD 9                 // 2*RADIUS+1
#define NB 16
#define NC 256
#define NH 96
#define NW 96
#define TYR 4                // output rows per CTA
#define PX 8                 // pixels per thread along x
#define NG (NW / PX)         // 12 x-groups per row
#define CC 8                 // channels staged per chunk
#define NCHUNK (NC / CC)     // 32
#define NTHREADS (NG * DD * TYR)   // 432
#define TH (TYR + 2 * RADIUS)      // 12 halo rows
#define TW (NW + 2 * RADIUS)       // 104 halo cols (keeps 16B alignment)
#define T_FLOATS (CC * TH * TW)    // 9984
#define S_FLOATS (CC * TYR * NW)   // 3072
#define BUF_FLOATS (T_FLOATS + S_FLOATS)   // 13056
#define SMEM_FLOATS (2 * BUF_FLOATS)       // 26112 -> 104448 bytes

__device__ __forceinline__ void cp16(uint32_t dst_smem, const void* src) {
    asm volatile("cp.async.cg.shared.global [%0], [%1], 16;\n"
                 :: "r"(dst_smem), "l"(src));
}
__device__ __forceinline__ void cp_commit() {
    asm volatile("cp.async.commit_group;\n" ::: "memory");
}
__device__ __forceinline__ void cp_wait1() {
    asm volatile("cp.async.wait_group 1;\n" ::: "memory");
}
__device__ __forceinline__ void cp_wait0() {
    asm volatile("cp.async.wait_group 0;\n" ::: "memory");
}

// Stage one 8-channel chunk (t halo tile + s tile) into a smem buffer via cp.async.
// Padding positions are never written (pre-zeroed once at kernel start).
__device__ __forceinline__ void stage_chunk(
    uint32_t tb_s, uint32_t sb_s,
    const float* __restrict__ ft_b, const float* __restrict__ fs_b,
    int c0, int y0, int tid)
{
    // t: CC*TH rows, 24 float4 of valid data per row (cols 4..99 in smem)
    const int T_SLOTS = CC * TH * 24;   // 2304
    for (int slot = tid; slot < T_SLOTS; slot += NTHREADS) {
        int c   = slot / (TH * 24);
        int rem = slot - c * (TH * 24);
        int ro  = rem / 24;
        int q   = rem - ro * 24;
        int gr  = y0 + ro - RADIUS;
        if ((unsigned)gr < NH) {
            uint32_t dst = tb_s + (((c * TH + ro) * TW + RADIUS + q * 4) << 2);
            const float* src = ft_b + ((size_t)(c0 + c) * NH + gr) * NW + q * 4;
            cp16(dst, src);
        }
    }
    // s: CC*TYR rows, 24 float4 per row
    const int S_SLOTS = CC * TYR * 24;  // 768
    for (int slot = tid; slot < S_SLOTS; slot += NTHREADS) {
        int c   = slot / (TYR * 24);
        int rem = slot - c * (TYR * 24);
        int ro  = rem / 24;
        int q   = rem - ro * 24;
        uint32_t dst = sb_s + (((c * TYR + ro) * NW + q * 4) << 2);
        const float* src = fs_b + ((size_t)(c0 + c) * NH + (y0 + ro)) * NW + q * 4;
        cp16(dst, src);
    }
}

__global__ __launch_bounds__(NTHREADS, 1)
void corr_kernel(const float* __restrict__ fs, const float* __restrict__ ft,
                 float* __restrict__ out)
{
    extern __shared__ float smem[];

    const int b   = blockIdx.y;
    const int y0  = blockIdx.x * TYR;
    const int tid = threadIdx.x;
    const int g   = tid % NG;              // x-group
    const int dy  = (tid / NG) % DD;       // this thread's dy plane
    const int r   = tid / (NG * DD);       // row within tile
    const int x0  = g * PX;

    // buffer layout: [t0][s0][t1][s1]
    float* tbuf[2] = { smem,              smem + BUF_FLOATS };
    float* sbuf[2] = { smem + T_FLOATS,   smem + BUF_FLOATS + T_FLOATS };
    const uint32_t smem_s = (uint32_t)__cvta_generic_to_shared(smem);
    const uint32_t tb_s[2] = { smem_s, smem_s + BUF_FLOATS * 4u };
    const uint32_t sb_s[2] = { smem_s + T_FLOATS * 4u,
                               smem_s + (BUF_FLOATS + T_FLOATS) * 4u };

    // Zero all smem once (padding stays zero for all chunks).
    for (int i = tid; i < SMEM_FLOATS; i += NTHREADS) smem[i] = 0.f;
    __syncthreads();

    float acc[PX * DD];
#pragma unroll
    for (int i = 0; i < PX * DD; ++i) acc[i] = 0.f;

    const float* fs_b = fs + (size_t)b * NC * NH * NW;
    const float* ft_b = ft + (size_t)b * NC * NH * NW;

    // Prologue: stage chunk 0 into buffer 0
    stage_chunk(tb_s[0], sb_s[0], ft_b, fs_b, 0, y0, tid);
    cp_commit();

    for (int k = 0; k < NCHUNK; ++k) {
        const int cur = k & 1;
        if (k + 1 < NCHUNK) {
            stage_chunk(tb_s[cur ^ 1], sb_s[cur ^ 1], ft_b, fs_b,
                        (k + 1) * CC, y0, tid);
            cp_commit();
            cp_wait1();          // chunk k's group done, chunk k+1 in flight
        } else {
            cp_wait0();
        }
        __syncthreads();         // chunk k visible to all threads

        const float* t_sh = tbuf[cur];
        const float* s_sh = sbuf[cur];

#pragma unroll
        for (int c = 0; c < CC; ++c) {
            const float* tp = t_sh + (c * TH + (r + dy)) * TW + x0;
            const float* sp = s_sh + (c * TYR + r) * NW + x0;

            float4 t0 = *(const float4*)(tp);
            float4 t1 = *(const float4*)(tp + 4);
            float4 t2 = *(const float4*)(tp + 8);
            float4 t3 = *(const float4*)(tp + 12);
            float tt[16] = {t0.x, t0.y, t0.z, t0.w,  t1.x, t1.y, t1.z, t1.w,
                            t2.x, t2.y, t2.z, t2.w,  t3.x, t3.y, t3.z, t3.w};

            float4 s0 = *(const float4*)(sp);
            float4 s1 = *(const float4*)(sp + 4);
            float ss[8] = {s0.x, s0.y, s0.z, s0.w,  s1.x, s1.y, s1.z, s1.w};

#pragma unroll
            for (int p = 0; p < PX; ++p) {
#pragma unroll
                for (int dx = 0; dx < DD; ++dx) {
                    acc[p * DD + dx] = fmaf(ss[p], tt[p + dx], acc[p * DD + dx]);
                }
            }
        }
        __syncthreads();         // all readers done before buffer is re-staged
    }

    // Epilogue: out[b, dy*9+dx, y, x0..x0+7], scaled by 1/C
    const float scale = 1.0f / (float)NC;
    const int y = y0 + r;
    float* ob = out + (((size_t)b * (DD * DD) + dy * DD) * NH + y) * NW + x0;
#pragma unroll
    for (int dx = 0; dx < DD; ++dx) {
        float4 o0, o1;
        o0.x = acc[0 * DD + dx] * scale;
        o0.y = acc[1 * DD + dx] * scale;
        o0.z = acc[2 * DD + dx] * scale;
        o0.w = acc[3 * DD + dx] * scale;
        o1.x = acc[4 * DD + dx] * scale;
        o1.y = acc[5 * DD + dx] * scale;
        o1.z = acc[6 * DD + dx] * scale;
        o1.w = acc[7 * DD + dx] * scale;
        float* op = ob + (size_t)dx * NH * NW;
        *(float4*)(op)     = o0;
        *(float4*)(op + 4) = o1;
    }
}

extern "C" void kernel_launch(void* const* d_in, const int* in_sizes, int n_in,
                              void* d_out, int out_size)
{
    const float* fs = (const float*)d_in[0];   // feat_s
    const float* ft = (const float*)d_in[1];   // feat_t
    float* out = (float*)d_out;

    size_t smem_bytes = (size_t)SMEM_FLOATS * sizeof(float);   // 104448
    cudaFuncSetAttribute(corr_kernel, cudaFuncAttributeMaxDynamicSharedMemorySize,
                         (int)smem_bytes);

    dim3 grid(NH / TYR, NB);   // (24, 16)
    corr_kernel<<<grid, NTHREADS, smem_bytes>>>(fs, ft, out);
}

// round 3
// speedup vs baseline: 2.4844x; 1.0953x over previous
#include <cuda_runtime.h>
#include <cstdint>

#define RADIUS 4
#define DD 9                 // 2*RADIUS+1
#define NB 16
#define NC 256
#define NH 96
#define NW 96
#define TYR 2                // output rows per CTA
#define PX 8                 // pixels per thread along x
#define NG (NW / PX)         // 12 x-groups per row
#define CC 8                 // channels staged per chunk
#define NCHUNK (NC / CC)     // 32
#define NCOMPUTE (NG * DD * TYR)   // 216 compute threads
#define BLOCK 224                  // 7 full warps
#define TH (TYR + 2 * RADIUS)      // 10 halo rows
#define TW (NW + 2 * RADIUS)       // 104 halo cols (16B-aligned rows)
#define T_FLOATS (CC * TH * TW)    // 8320
#define S_FLOATS (CC * TYR * NW)   // 1536
#define BUF_FLOATS (T_FLOATS + S_FLOATS)   // 9856
#define SMEM_FLOATS (2 * BUF_FLOATS)       // 19712 -> 78848 bytes

union F2U { float2 f; unsigned long long u; };

__device__ __forceinline__ float2 ffma2(float2 a, float2 b, float2 c) {
    F2U ua, ub, uc, ud;
    ua.f = a; ub.f = b; uc.f = c;
    asm("fma.rn.f32x2 %0, %1, %2, %3;"
        : "=l"(ud.u) : "l"(ua.u), "l"(ub.u), "l"(uc.u));
    return ud.f;
}

__device__ __forceinline__ void cp16(uint32_t dst_smem, const void* src) {
    asm volatile("cp.async.cg.shared.global [%0], [%1], 16;\n"
                 :: "r"(dst_smem), "l"(src));
}
__device__ __forceinline__ void cp_commit() {
    asm volatile("cp.async.commit_group;\n" ::: "memory");
}
__device__ __forceinline__ void cp_wait1() {
    asm volatile("cp.async.wait_group 1;\n" ::: "memory");
}
__device__ __forceinline__ void cp_wait0() {
    asm volatile("cp.async.wait_group 0;\n" ::: "memory");
}

// Stage one 8-channel chunk (t halo tile + s tile) via cp.async.
// Padding rows are never written (smem pre-zeroed once).
__device__ __forceinline__ void stage_chunk(
    uint32_t tb_s, uint32_t sb_s,
    const float* __restrict__ ft_b, const float* __restrict__ fs_b,
    int c0, int y0, int tid)
{
    const int T_SLOTS = CC * TH * 24;   // 1920 float4s
    for (int slot = tid; slot < T_SLOTS; slot += BLOCK) {
        int c   = slot / (TH * 24);
        int rem = slot - c * (TH * 24);
        int ro  = rem / 24;
        int q   = rem - ro * 24;
        int gr  = y0 + ro - RADIUS;
        if ((unsigned)gr < NH) {
            uint32_t dst = tb_s + (((c * TH + ro) * TW + RADIUS + q * 4) << 2);
            const float* src = ft_b + ((size_t)(c0 + c) * NH + gr) * NW + q * 4;
            cp16(dst, src);
        }
    }
    const int S_SLOTS = CC * TYR * 24;  // 384 float4s
    for (int slot = tid; slot < S_SLOTS; slot += BLOCK) {
        int c   = slot / (TYR * 24);
        int rem = slot - c * (TYR * 24);
        int ro  = rem / 24;
        int q   = rem - ro * 24;
        uint32_t dst = sb_s + (((c * TYR + ro) * NW + q * 4) << 2);
        const float* src = fs_b + ((size_t)(c0 + c) * NH + (y0 + ro)) * NW + q * 4;
        cp16(dst, src);
    }
}

__global__ __launch_bounds__(BLOCK, 2)
void corr_kernel(const float* __restrict__ fs, const float* __restrict__ ft,
                 float* __restrict__ out)
{
    extern __shared__ float smem[];

    const int b   = blockIdx.y;
    const int y0  = blockIdx.x * TYR;
    const int tid = threadIdx.x;
    const int g   = tid % NG;              // x-group
    const int dy  = (tid / NG) % DD;       // dy plane
    const int r   = tid / (NG * DD);       // row within tile (0..TYR-1), junk for tid>=216
    const int x0  = g * PX;
    const bool active = (tid < NCOMPUTE);

    float* tbuf[2] = { smem,            smem + BUF_FLOATS };
    float* sbuf[2] = { smem + T_FLOATS, smem + BUF_FLOATS + T_FLOATS };
    const uint32_t smem_s = (uint32_t)__cvta_generic_to_shared(smem);
    const uint32_t tb_s[2] = { smem_s, smem_s + BUF_FLOATS * 4u };
    const uint32_t sb_s[2] = { smem_s + T_FLOATS * 4u,
                               smem_s + (BUF_FLOATS + T_FLOATS) * 4u };

    for (int i = tid; i < SMEM_FLOATS; i += BLOCK) smem[i] = 0.f;
    __syncthreads();

    // acc2[pp][dx] = (acc[2pp][dx], acc[2pp+1][dx])
    float2 acc2[4][DD];
#pragma unroll
    for (int pp = 0; pp < 4; ++pp)
#pragma unroll
        for (int dx = 0; dx < DD; ++dx) acc2[pp][dx] = make_float2(0.f, 0.f);

    const float* fs_b = fs + (size_t)b * NC * NH * NW;
    const float* ft_b = ft + (size_t)b * NC * NH * NW;

    stage_chunk(tb_s[0], sb_s[0], ft_b, fs_b, 0, y0, tid);
    cp_commit();

    for (int k = 0; k < NCHUNK; ++k) {
        const int cur = k & 1;
        if (k + 1 < NCHUNK) {
            stage_chunk(tb_s[cur ^ 1], sb_s[cur ^ 1], ft_b, fs_b,
                        (k + 1) * CC, y0, tid);
            cp_commit();
            cp_wait1();
        } else {
            cp_wait0();
        }
        __syncthreads();

        if (active) {
            const float* t_sh = tbuf[cur];
            const float* s_sh = sbuf[cur];
#pragma unroll
            for (int c = 0; c < CC; ++c) {
                const float* tp = t_sh + (c * TH + (r + dy)) * TW + x0;
                const float* sp = s_sh + (c * TYR + r) * NW + x0;

                float4 T0 = *(const float4*)(tp);
                float4 T1 = *(const float4*)(tp + 4);
                float4 T2 = *(const float4*)(tp + 8);
                float4 T3 = *(const float4*)(tp + 12);
                float4 S0 = *(const float4*)(sp);
                float4 S1 = *(const float4*)(sp + 4);

                // te[k] = (tt[2k], tt[2k+1]) -- aligned pairs, no MOVs needed
                float2 te[8] = { {T0.x,T0.y},{T0.z,T0.w},{T1.x,T1.y},{T1.z,T1.w},
                                 {T2.x,T2.y},{T2.z,T2.w},{T3.x,T3.y},{T3.z,T3.w} };
                float2 se[4] = { {S0.x,S0.y},{S0.z,S0.w},{S1.x,S1.y},{S1.z,S1.w} };

#pragma unroll
                for (int pp = 0; pp < 4; ++pp) {
                    // even dx = 2m: packed FFMA2, multiplier pair te[pp+m]
#pragma unroll
                    for (int m = 0; m <= 4; ++m) {
                        acc2[pp][2 * m] = ffma2(se[pp], te[pp + m], acc2[pp][2 * m]);
                    }
                    // odd dx = 2m+1: scalar FFMA
#pragma unroll
                    for (int m = 0; m < 4; ++m) {
                        acc2[pp][2 * m + 1].x =
                            fmaf(se[pp].x, te[pp + m].y,     acc2[pp][2 * m + 1].x);
                        acc2[pp][2 * m + 1].y =
                            fmaf(se[pp].y, te[pp + m + 1].x, acc2[pp][2 * m + 1].y);
                    }
                }
            }
        }
        __syncthreads();
    }

    if (active) {
        const float scale = 1.0f / (float)NC;
        const int y = y0 + r;
        float* ob = out + (((size_t)b * (DD * DD) + dy * DD) * NH + y) * NW + x0;
#pragma unroll
        for (int dx = 0; dx < DD; ++dx) {
            float4 o0, o1;
            o0.x = acc2[0][dx].x * scale;
            o0.y = acc2[0][dx].y * scale;
            o0.z = acc2[1][dx].x * scale;
            o0.w = acc2[1][dx].y * scale;
            o1.x = acc2[2][dx].x * scale;
            o1.y = acc2[2][dx].y * scale;
            o1.z = acc2[3][dx].x * scale;
            o1.w = acc2[3][dx].y * scale;
            float* op = ob + (size_t)dx * NH * NW;
            *(float4*)(op)     = o0;
            *(float4*)(op + 4) = o1;
        }
    }
}

extern "C" void kernel_launch(void* const* d_in, const int* in_sizes, int n_in,
                              void* d_out, int out_size)
{
    const float* fs = (const float*)d_in[0];   // feat_s
    const float* ft = (const float*)d_in[1];   // feat_t
    float* out = (float*)d_out;

    size_t smem_bytes = (size_t)SMEM_FLOATS * sizeof(float);   // 78848
    cudaFuncSetAttribute(corr_kernel, cudaFuncAttributeMaxDynamicSharedMemorySize,
                         (int)smem_bytes);

    dim3 grid(NH / TYR, NB);   // (48, 16)
    corr_kernel<<<grid, BLOCK, smem_bytes>>>(fs, ft, out);
}

// round 4
// speedup vs baseline: 2.4855x; 1.0005x over previous
#include <cuda_runtime.h>
#include <cstdint>

#define RADIUS 4
#define DD 9                 // 2*RADIUS+1
#define NB 16
#define NC 256
#define NH 96
#define NW 96
#define TYR 2                // output rows per CTA
#define PX 8                 // pixels per thread along x
#define NG (NW / PX)         // 12 x-groups per row
#define CC 8                 // channels staged per chunk
#define NCHUNK (NC / CC)     // 32
#define NCOMPUTE (NG * DD * TYR)   // 216 compute threads
#define BLOCK 224                  // 7 full warps
#define TH (TYR + 2 * RADIUS)      // 10 halo rows
#define TW (NW + 2 * RADIUS)       // 104 halo cols (16B-aligned rows)
#define T_FLOATS (CC * TH * TW)    // 8320
#define S_FLOATS (CC * TYR * NW)   // 1536
#define BUF_FLOATS (T_FLOATS + S_FLOATS)   // 9856
#define SMEM_FLOATS (2 * BUF_FLOATS)       // 19712 -> 78848 bytes

union F2U { float2 f; unsigned long long u; };

__device__ __forceinline__ float2 ffma2(float2 a, float2 b, float2 c) {
    F2U ua, ub, uc, ud;
    ua.f = a; ub.f = b; uc.f = c;
    asm("fma.rn.f32x2 %0, %1, %2, %3;"
        : "=l"(ud.u) : "l"(ua.u), "l"(ub.u), "l"(uc.u));
    return ud.f;
}

__device__ __forceinline__ void cp16(uint32_t dst_smem, const void* src) {
    asm volatile("cp.async.cg.shared.global [%0], [%1], 16;\n"
                 :: "r"(dst_smem), "l"(src));
}
__device__ __forceinline__ void cp_commit() {
    asm volatile("cp.async.commit_group;\n" ::: "memory");
}
__device__ __forceinline__ void cp_wait1() {
    asm volatile("cp.async.wait_group 1;\n" ::: "memory");
}
__device__ __forceinline__ void cp_wait0() {
    asm volatile("cp.async.wait_group 0;\n" ::: "memory");
}

// Stage one 8-channel chunk (t halo tile + s tile) via cp.async.
// Padding rows are never written (smem pre-zeroed once).
__device__ __forceinline__ void stage_chunk(
    uint32_t tb_s, uint32_t sb_s,
    const float* __restrict__ ft_b, const float* __restrict__ fs_b,
    int c0, int y0, int tid)
{
    const int T_SLOTS = CC * TH * 24;   // 1920 float4s
    for (int slot = tid; slot < T_SLOTS; slot += BLOCK) {
        int c   = slot / (TH * 24);
        int rem = slot - c * (TH * 24);
        int ro  = rem / 24;
        int q   = rem - ro * 24;
        int gr  = y0 + ro - RADIUS;
        if ((unsigned)gr < NH) {
            uint32_t dst = tb_s + (((c * TH + ro) * TW + RADIUS + q * 4) << 2);
            const float* src = ft_b + ((size_t)(c0 + c) * NH + gr) * NW + q * 4;
            cp16(dst, src);
        }
    }
    const int S_SLOTS = CC * TYR * 24;  // 384 float4s
    for (int slot = tid; slot < S_SLOTS; slot += BLOCK) {
        int c   = slot / (TYR * 24);
        int rem = slot - c * (TYR * 24);
        int ro  = rem / 24;
        int q   = rem - ro * 24;
        uint32_t dst = sb_s + (((c * TYR + ro) * NW + q * 4) << 2);
        const float* src = fs_b + ((size_t)(c0 + c) * NH + (y0 + ro)) * NW + q * 4;
        cp16(dst, src);
    }
}

__global__ __launch_bounds__(BLOCK, 2)
void corr_kernel(const float* __restrict__ fs, const float* __restrict__ ft,
                 float* __restrict__ out)
{
    extern __shared__ float smem[];

    const int b   = blockIdx.y;
    const int y0  = blockIdx.x * TYR;
    const int tid = threadIdx.x;
    const int g   = tid % NG;              // x-group
    const int dy  = (tid / NG) % DD;       // dy plane
    const int r   = tid / (NG * DD);       // row within tile (0..TYR-1), junk for tid>=216
    const int x0  = g * PX;
    const bool active = (tid < NCOMPUTE);

    float* tbuf[2] = { smem,            smem + BUF_FLOATS };
    float* sbuf[2] = { smem + T_FLOATS, smem + BUF_FLOATS + T_FLOATS };
    const uint32_t smem_s = (uint32_t)__cvta_generic_to_shared(smem);
    const uint32_t tb_s[2] = { smem_s, smem_s + BUF_FLOATS * 4u };
    const uint32_t sb_s[2] = { smem_s + T_FLOATS * 4u,
                               smem_s + (BUF_FLOATS + T_FLOATS) * 4u };

    for (int i = tid; i < SMEM_FLOATS; i += BLOCK) smem[i] = 0.f;
    __syncthreads();

    // acc2[pp][dx] = (acc[2pp][dx], acc[2pp+1][dx])
    float2 acc2[4][DD];
#pragma unroll
    for (int pp = 0; pp < 4; ++pp)
#pragma unroll
        for (int dx = 0; dx < DD; ++dx) acc2[pp][dx] = make_float2(0.f, 0.f);

    const float* fs_b = fs + (size_t)b * NC * NH * NW;
    const float* ft_b = ft + (size_t)b * NC * NH * NW;

    stage_chunk(tb_s[0], sb_s[0], ft_b, fs_b, 0, y0, tid);
    cp_commit();

    for (int k = 0; k < NCHUNK; ++k) {
        const int cur = k & 1;
        if (k + 1 < NCHUNK) {
            stage_chunk(tb_s[cur ^ 1], sb_s[cur ^ 1], ft_b, fs_b,
                        (k + 1) * CC, y0, tid);
            cp_commit();
            cp_wait1();
        } else {
            cp_wait0();
        }
        __syncthreads();

        if (active) {
            const float* t_sh = tbuf[cur];
            const float* s_sh = sbuf[cur];
#pragma unroll
            for (int c = 0; c < CC; ++c) {
                const float* tp = t_sh + (c * TH + (r + dy)) * TW + x0;
                const float* sp = s_sh + (c * TYR + r) * NW + x0;

                float4 T0 = *(const float4*)(tp);
                float4 T1 = *(const float4*)(tp + 4);
                float4 T2 = *(const float4*)(tp + 8);
                float4 T3 = *(const float4*)(tp + 12);
                float4 S0 = *(const float4*)(sp);
                float4 S1 = *(const float4*)(sp + 4);

                // te[k] = (tt[2k], tt[2k+1]) -- aligned pairs, no MOVs needed
                float2 te[8] = { {T0.x,T0.y},{T0.z,T0.w},{T1.x,T1.y},{T1.z,T1.w},
                                 {T2.x,T2.y},{T2.z,T2.w},{T3.x,T3.y},{T3.z,T3.w} };
                float2 se[4] = { {S0.x,S0.y},{S0.z,S0.w},{S1.x,S1.y},{S1.z,S1.w} };

#pragma unroll
                for (int pp = 0; pp < 4; ++pp) {
                    // even dx = 2m: packed FFMA2, multiplier pair te[pp+m]
#pragma unroll
                    for (int m = 0; m <= 4; ++m) {
                        acc2[pp][2 * m] = ffma2(se[pp], te[pp + m], acc2[pp][2 * m]);
                    }
                    // odd dx = 2m+1: scalar FFMA
#pragma unroll
                    for (int m = 0; m < 4; ++m) {
                        acc2[pp][2 * m + 1].x =
                            fmaf(se[pp].x, te[pp + m].y,     acc2[pp][2 * m + 1].x);
                        acc2[pp][2 * m + 1].y =
                            fmaf(se[pp].y, te[pp + m + 1].x, acc2[pp][2 * m + 1].y);
                    }
                }
            }
        }
        __syncthreads();
    }

    if (active) {
        const float scale = 1.0f / (float)NC;
        const int y = y0 + r;
        float* ob = out + (((size_t)b * (DD * DD) + dy * DD) * NH + y) * NW + x0;
#pragma unroll
        for (int dx = 0; dx < DD; ++dx) {
            float4 o0, o1;
            o0.x = acc2[0][dx].x * scale;
            o0.y = acc2[0][dx].y * scale;
            o0.z = acc2[1][dx].x * scale;
            o0.w = acc2[1][dx].y * scale;
            o1.x = acc2[2][dx].x * scale;
            o1.y = acc2[2][dx].y * scale;
            o1.z = acc2[3][dx].x * scale;
            o1.w = acc2[3][dx].y * scale;
            float* op = ob + (size_t)dx * NH * NW;
            *(float4*)(op)     = o0;
            *(float4*)(op + 4) = o1;
        }
    }
}

extern "C" void kernel_launch(void* const* d_in, const int* in_sizes, int n_in,
                              void* d_out, int out_size)
{
    const float* fs = (const float*)d_in[0];   // feat_s
    const float* ft = (const float*)d_in[1];   // feat_t
    float* out = (float*)d_out;

    size_t smem_bytes = (size_t)SMEM_FLOATS * sizeof(float);   // 78848
    cudaFuncSetAttribute(corr_kernel, cudaFuncAttributeMaxDynamicSharedMemorySize,
                         (int)smem_bytes);

    dim3 grid(NH / TYR, NB);   // (48, 16)
    corr_kernel<<<grid, BLOCK, smem_bytes>>>(fs, ft, out);
}